// round 17
// baseline (speedup 1.0000x reference)
#include <cuda_runtime.h>
#include <cstdint>

// B=4, H=16, S=1024, D=64 ; out = [O (64*1024*64 f32)] ++ [attn (64*1024*1024 f32)]
#define SQ 1024
#define DD 64
#define QT 32
#define NBH 64
#define QPL 32             // u32 per swizzled plane row (128B)
#define QPLANE (32*QPL)    // u32 per Q plane
#define KPL1 (128*QPL)     // u32 per 128-key K plane = 4096
#define KBUF1 (2*KPL1)     // u32 per K buffer (hi+lo) = 8192
#define VPS 136            // u32 row stride of transposed V plane (64 pairs x {hi,lo} + pad)
#define VPBUF (64*VPS)     // u32 per V buffer = 8704
#define SLABU (2*VPBUF)    // 17408 u32 >= 2*KBUF1
#define OS 68              // O-reduction plane row stride (f32)

__device__ __forceinline__ uint32_t packbf(float lo, float hi) {
    uint32_t r;
    asm("cvt.rn.bf16x2.f32 %0, %1, %2;" : "=r"(r) : "f"(hi), "f"(lo));
    return r;
}
__device__ __forceinline__ float bf_lo(uint32_t p) { return __uint_as_float(p << 16); }
__device__ __forceinline__ float bf_hi(uint32_t p) { return __uint_as_float(p & 0xffff0000u); }

__device__ __forceinline__ void mma16(float* c, uint32_t a0, uint32_t a1, uint32_t a2, uint32_t a3,
                                      uint32_t b0, uint32_t b1) {
    asm volatile("mma.sync.aligned.m16n8k16.row.col.f32.bf16.bf16.f32 "
                 "{%0,%1,%2,%3}, {%4,%5,%6,%7}, {%8,%9}, {%0,%1,%2,%3};\n"
                 : "+f"(c[0]), "+f"(c[1]), "+f"(c[2]), "+f"(c[3])
                 : "r"(a0), "r"(a1), "r"(a2), "r"(a3), "r"(b0), "r"(b1));
}
__device__ __forceinline__ void ldsm4(uint32_t& r0, uint32_t& r1, uint32_t& r2, uint32_t& r3,
                                      uint32_t addr) {
    asm volatile("ldmatrix.sync.aligned.m8n8.x4.shared.b16 {%0,%1,%2,%3}, [%4];"
                 : "=r"(r0), "=r"(r1), "=r"(r2), "=r"(r3) : "r"(addr));
}

__global__ __launch_bounds__(1024, 1)
void attn_occ2_kernel(const float* __restrict__ Q,
                      const float* __restrict__ K,
                      const float* __restrict__ V,
                      const float* __restrict__ bias,
                      float* __restrict__ out)
{
    extern __shared__ uint32_t smu[];
    uint32_t* sQh  = smu;                          // QPLANE
    uint32_t* sQl  = sQh + QPLANE;                 // QPLANE
    float*    sRed = (float*)(sQl + QPLANE);       // 32*16
    uint32_t* slab = (uint32_t*)(sRed + 32 * 16);  // SLABU (K bufs / V planes)
    float*    sOr  = (float*)(slab + SLABU);       // 8*32*OS

    const int t    = threadIdx.x;
    const int lane = t & 31;
    const int w    = t >> 5;                       // 0..31
    const int qh   = w >> 4;                       // 0..1
    const int cg   = w & 15;                       // 0..15 (phases 1-2)
    const int gid  = lane >> 2;
    const int tig  = lane & 3;
    const int rowA = qh * 16 + gid;

    const int bh = blockIdx.y;
    const int q0 = blockIdx.x * QT;

    const float* Qb = Q + ((size_t)bh * SQ + q0) * DD;
    const float* Kb = K + (size_t)bh * SQ * DD;
    const float* Vb = V + (size_t)bh * SQ * DD;
    float* outO = out + ((size_t)bh * SQ + q0) * DD;
    float* outA = out + (size_t)NBH * SQ * DD + ((size_t)bh * SQ + q0) * SQ;

    // ---- stage Q: swizzled 128B-row bf16 hi/lo planes ----
    if (t < 256) {
        int r = t >> 3, dq8 = t & 7;
        const float* qr = Qb + r * DD + dq8 * 8;
        float4 qa = *(const float4*)qr;
        float4 qb = *(const float4*)(qr + 4);
        uint32_t h0 = packbf(qa.x, qa.y), h1 = packbf(qa.z, qa.w);
        uint32_t h2 = packbf(qb.x, qb.y), h3 = packbf(qb.z, qb.w);
        uint32_t l0 = packbf(qa.x - bf_lo(h0), qa.y - bf_hi(h0));
        uint32_t l1 = packbf(qa.z - bf_lo(h1), qa.w - bf_hi(h1));
        uint32_t l2 = packbf(qb.x - bf_lo(h2), qb.y - bf_hi(h2));
        uint32_t l3 = packbf(qb.z - bf_lo(h3), qb.w - bf_hi(h3));
        uint32_t off = r * QPL + (((dq8 * 16) ^ ((r & 7) << 4)) >> 2);
        *(uint4*)&sQh[off] = make_uint4(h0, h1, h2, h3);
        *(uint4*)&sQl[off] = make_uint4(l0, l1, l2, l3);
    }

    float acc[8][4];
    #pragma unroll
    for (int j = 0; j < 8; j++) {
        acc[j][0] = 0.f; acc[j][1] = 0.f; acc[j][2] = 0.f; acc[j][3] = 0.f;
    }

    // ====== phase 1: scores = Q K^T (3xBF16 k16), 128-key chunks, 1 tile/warp ======
    const int kkey = t >> 3;          // 0..127 (full chunk per staging call)
    const int kdq8 = t & 7;
    const uint32_t kstXor = ((uint32_t)(kkey & 7)) << 4;
    float4 ka, kb;

    #define LDK(chunk) do {                                                 \
        const float* _s = Kb + ((size_t)(chunk) * 128 + kkey) * DD + kdq8 * 8; \
        ka = *(const float4*)_s;                                            \
        kb = *(const float4*)(_s + 4);                                      \
    } while (0)

    #define STK(bufp) do {                                                  \
        uint32_t _off = kkey * QPL + (((kdq8 * 16) ^ kstXor) >> 2);         \
        uint32_t h0 = packbf(ka.x, ka.y), h1 = packbf(ka.z, ka.w);          \
        uint32_t h2 = packbf(kb.x, kb.y), h3 = packbf(kb.z, kb.w);          \
        uint32_t l0 = packbf(ka.x - bf_lo(h0), ka.y - bf_hi(h0));           \
        uint32_t l1 = packbf(ka.z - bf_lo(h1), ka.w - bf_hi(h1));           \
        uint32_t l2 = packbf(kb.x - bf_lo(h2), kb.y - bf_hi(h2));           \
        uint32_t l3 = packbf(kb.z - bf_lo(h3), kb.w - bf_hi(h3));           \
        *(uint4*)&(bufp)[_off] = make_uint4(h0, h1, h2, h3);                \
        *(uint4*)&(bufp)[KPL1 + _off] = make_uint4(l0, l1, l2, l3);         \
    } while (0)

    const int g  = lane >> 3;
    const int l7 = lane & 7;
    const uint32_t sQhA  = (uint32_t)__cvta_generic_to_shared(sQh);
    const uint32_t slabA = (uint32_t)__cvta_generic_to_shared(slab);
    const int aRow = qh * 16 + (g & 1) * 8 + l7;
    const uint32_t aFixed = sQhA + (uint32_t)(aRow * 128);
    const uint32_t aKX  = (uint32_t)((g >> 1) * 16);
    const uint32_t aXor = ((uint32_t)(aRow & 7)) << 4;
    const uint32_t bRowOff = (uint32_t)((cg * 8 + l7) * 128);
    const uint32_t bG16 = (uint32_t)(g * 16);
    const uint32_t bXor = ((uint32_t)l7) << 4;

    LDK(0); STK(slab);
    LDK(1);
    __syncthreads();

    #pragma unroll
    for (int c = 0; c < 8; c++) {
        const uint32_t kbase = slabA + (uint32_t)((c & 1) * KBUF1 * 4);
        float* cc = acc[c];

        #pragma unroll
        for (int dsp = 0; dsp < 2; dsp++) {
            const uint32_t bt = ((uint32_t)(dsp * 64) + bG16) ^ bXor;
            uint32_t bH0, bH1, bH2, bH3, bL0, bL1, bL2, bL3;
            ldsm4(bH0, bH1, bH2, bH3, kbase + bRowOff + bt);
            ldsm4(bL0, bL1, bL2, bL3, kbase + bRowOff + bt + KPL1 * 4);
            #pragma unroll
            for (int e = 0; e < 2; e++) {
                const int ds = 2 * dsp + e;
                const uint32_t at = (uint32_t)(ds * 32 + aKX) ^ aXor;
                uint32_t aH0, aH1, aH2, aH3, aL0, aL1, aL2, aL3;
                ldsm4(aH0, aH1, aH2, aH3, aFixed + at);
                ldsm4(aL0, aL1, aL2, aL3, aFixed + at + QPLANE * 4);
                uint32_t B0 = e ? bH2 : bH0, B1 = e ? bH3 : bH1;
                uint32_t C0 = e ? bL2 : bL0, C1 = e ? bL3 : bL1;
                mma16(cc, aH0, aH1, aH2, aH3, B0, B1);
                mma16(cc, aH0, aH1, aH2, aH3, C0, C1);
                mma16(cc, aL0, aL1, aL2, aL3, B0, B1);
            }
        }
        if (c < 7) { STK(slab + ((c + 1) & 1) * KBUF1); }
        if (c < 6) LDK(c + 2);
        __syncthreads();
    }

    // ---- V chunk-0 LDG prefetch (held through softmax: 8 regs) ----
    const int vpair = t & 63;        // key pair within 128-key chunk
    const int vdq4  = t >> 6;        // 0..15 d-quad
    float4 va, vb2;
    #define LDV(chunk) do {                                                 \
        const float* _s = Vb + ((size_t)(chunk) * 128 + 2 * vpair) * DD + vdq4 * 4; \
        va  = *(const float4*)_s;                                           \
        vb2 = *(const float4*)(_s + DD);                                    \
    } while (0)
    #define STV(chunk) do {                                                 \
        uint32_t* _p = slab + (((chunk) & 1) ? VPBUF : 0);                  \
        float _ea[4] = {va.x, va.y, va.z, va.w};                            \
        float _eb[4] = {vb2.x, vb2.y, vb2.z, vb2.w};                        \
        _Pragma("unroll")                                                   \
        for (int _i = 0; _i < 4; _i++) {                                    \
            uint32_t _h = packbf(_ea[_i], _eb[_i]);                         \
            uint32_t _l = packbf(_ea[_i] - bf_lo(_h), _eb[_i] - bf_hi(_h)); \
            *(uint2*)&_p[(vdq4 * 4 + _i) * VPS + vpair * 2] = make_uint2(_h, _l); \
        }                                                                   \
    } while (0)

    LDV(0);

    // ================= phase 2: scale + bias + softmax, attn write from regs =================
    const float scale = 0.125f;
    float m1 = -1e30f, m2 = -1e30f;
    #pragma unroll
    for (int j = 0; j < 8; j++) {
        const int col = j * 128 + cg * 8 + 2 * tig;
        float2 b1v = *(const float2*)&bias[(size_t)(q0 + rowA) * SQ + col];
        float2 b2v = *(const float2*)&bias[(size_t)(q0 + rowA + 8) * SQ + col];
        acc[j][0] = acc[j][0] * scale + b1v.x;
        acc[j][1] = acc[j][1] * scale + b1v.y;
        acc[j][2] = acc[j][2] * scale + b2v.x;
        acc[j][3] = acc[j][3] * scale + b2v.y;
        m1 = fmaxf(m1, fmaxf(acc[j][0], acc[j][1]));
        m2 = fmaxf(m2, fmaxf(acc[j][2], acc[j][3]));
    }
    m1 = fmaxf(m1, __shfl_xor_sync(0xffffffffu, m1, 1));
    m1 = fmaxf(m1, __shfl_xor_sync(0xffffffffu, m1, 2));
    m2 = fmaxf(m2, __shfl_xor_sync(0xffffffffu, m2, 1));
    m2 = fmaxf(m2, __shfl_xor_sync(0xffffffffu, m2, 2));
    if (tig == 0) {
        sRed[rowA * 16 + cg]       = m1;
        sRed[(rowA + 8) * 16 + cg] = m2;
    }
    __syncthreads();
    m1 = -1e30f; m2 = -1e30f;
    #pragma unroll
    for (int i = 0; i < 16; i++) {
        m1 = fmaxf(m1, sRed[rowA * 16 + i]);
        m2 = fmaxf(m2, sRed[(rowA + 8) * 16 + i]);
    }
    float s1 = 0.f, s2 = 0.f;
    #pragma unroll
    for (int j = 0; j < 8; j++) {
        acc[j][0] = __expf(acc[j][0] - m1);
        acc[j][1] = __expf(acc[j][1] - m1);
        acc[j][2] = __expf(acc[j][2] - m2);
        acc[j][3] = __expf(acc[j][3] - m2);
        s1 += acc[j][0] + acc[j][1];
        s2 += acc[j][2] + acc[j][3];
    }
    s1 += __shfl_xor_sync(0xffffffffu, s1, 1);
    s1 += __shfl_xor_sync(0xffffffffu, s1, 2);
    s2 += __shfl_xor_sync(0xffffffffu, s2, 1);
    s2 += __shfl_xor_sync(0xffffffffu, s2, 2);
    __syncthreads();
    if (tig == 0) {
        sRed[rowA * 16 + cg]       = s1;
        sRed[(rowA + 8) * 16 + cg] = s2;
    }
    __syncthreads();
    s1 = 0.f; s2 = 0.f;
    #pragma unroll
    for (int i = 0; i < 16; i++) {
        s1 += sRed[rowA * 16 + i];
        s2 += sRed[(rowA + 8) * 16 + i];
    }
    const float inv1 = 1.0f / s1;
    const float inv2 = 1.0f / s2;
    #pragma unroll
    for (int j = 0; j < 8; j++) {
        acc[j][0] *= inv1; acc[j][1] *= inv1;
        acc[j][2] *= inv2; acc[j][3] *= inv2;
        const int col = j * 128 + cg * 8 + 2 * tig;
        *(float2*)&outA[(size_t)rowA * SQ + col]       = make_float2(acc[j][0], acc[j][1]);
        *(float2*)&outA[(size_t)(rowA + 8) * SQ + col] = make_float2(acc[j][2], acc[j][3]);
    }

    // ====== phase 3: O = P V (3xBF16 k16), P reread from attn (L2-hot), split dt ======
    STV(0);
    LDV(1);
    __syncthreads();   // publishes V chunk 0 AND attn writes (block-scope global visibility)

    const int dtg = (w >> 3) & 1;    // d half: dt 0..3 or 4..7
    const int cg3 = w & 7;           // key column group (8 keys per 64-group)
    float o[4][4];
    #pragma unroll
    for (int dt = 0; dt < 4; dt++) {
        o[dt][0] = 0.f; o[dt][1] = 0.f; o[dt][2] = 0.f; o[dt][3] = 0.f;
    }

    #pragma unroll
    for (int c = 0; c < 8; c++) {
        const uint32_t* vp = slab + ((c & 1) ? VPBUF : 0);

        // P fragments (k16 = sub0 keys ++ sub1 keys) from gmem attn
        const float* pr = outA + (size_t)rowA * SQ + c * 128 + cg3 * 8 + 2 * tig;
        float2 a0v = *(const float2*)pr;
        float2 a1v = *(const float2*)(pr + 8 * SQ);
        float2 a2v = *(const float2*)(pr + 64);
        float2 a3v = *(const float2*)(pr + 8 * SQ + 64);
        uint32_t pH0 = packbf(a0v.x, a0v.y);
        uint32_t pH1 = packbf(a1v.x, a1v.y);
        uint32_t pH2 = packbf(a2v.x, a2v.y);
        uint32_t pH3 = packbf(a3v.x, a3v.y);
        uint32_t pL0 = packbf(a0v.x - bf_lo(pH0), a0v.y - bf_hi(pH0));
        uint32_t pL1 = packbf(a1v.x - bf_lo(pH1), a1v.y - bf_hi(pH1));
        uint32_t pL2 = packbf(a2v.x - bf_lo(pH2), a2v.y - bf_hi(pH2));
        uint32_t pL3 = packbf(a3v.x - bf_lo(pH3), a3v.y - bf_hi(pH3));

        #pragma unroll
        for (int dt = 0; dt < 4; dt++) {
            const int dtA = dtg * 4 + dt;
            const uint32_t* row = vp + (dtA * 8 + gid) * VPS;
            uint2 B0 = *(const uint2*)&row[(cg3 * 4 + tig) * 2];        // sub0 pair {hi,lo}
            uint2 B1 = *(const uint2*)&row[(32 + cg3 * 4 + tig) * 2];   // sub1 pair {hi,lo}
            mma16(o[dt], pH0, pH1, pH2, pH3, B0.x, B1.x);
            mma16(o[dt], pH0, pH1, pH2, pH3, B0.y, B1.y);
            mma16(o[dt], pL0, pL1, pL2, pL3, B0.x, B1.x);
        }

        if (c < 7) STV(c + 1);
        if (c < 6) LDV(c + 2);
        __syncthreads();   // publish chunk c+1 planes; retire chunk c readers
    }

    // ---- cross-cg3 reduction of partial O, then coalesced store ----
    {
        float* myp = sOr + cg3 * (32 * OS);
        #pragma unroll
        for (int dt = 0; dt < 4; dt++) {
            const int dtA = dtg * 4 + dt;
            *(float2*)&myp[rowA * OS + dtA * 8 + 2 * tig]       = make_float2(o[dt][0], o[dt][1]);
            *(float2*)&myp[(rowA + 8) * OS + dtA * 8 + 2 * tig] = make_float2(o[dt][2], o[dt][3]);
        }
    }
    __syncthreads();
    if (t < 512) {
        int r = t >> 4, c4 = t & 15;
        float4 s = make_float4(0.f, 0.f, 0.f, 0.f);
        #pragma unroll
        for (int p = 0; p < 8; p++) {
            float4 v = *(float4*)&sOr[p * (32 * OS) + r * OS + c4 * 4];
            s.x += v.x; s.y += v.y; s.z += v.z; s.w += v.w;
        }
        *(float4*)&outO[(size_t)r * DD + c4 * 4] = s;
    }
}

extern "C" void kernel_launch(void* const* d_in, const int* in_sizes, int n_in,
                              void* d_out, int out_size)
{
    const float* Q    = (const float*)d_in[0];
    const float* K    = (const float*)d_in[1];
    const float* V    = (const float*)d_in[2];
    const float* bias = (const float*)d_in[3];
    float* out        = (float*)d_out;

    const size_t smem_u32 = (size_t)(2 * QPLANE) + 32 * 16 + SLABU + 8 * 32 * OS;
    const size_t smem_bytes = smem_u32 * sizeof(uint32_t);   // ~149.5 KB
    cudaFuncSetAttribute(attn_occ2_kernel,
                         cudaFuncAttributeMaxDynamicSharedMemorySize, (int)smem_bytes);

    dim3 grid(SQ / QT, NBH);
    attn_occ2_kernel<<<grid, 1024, smem_bytes>>>(Q, K, V, bias, out);
}